// round 1
// baseline (speedup 1.0000x reference)
#include <cuda_runtime.h>
#include <cuda_bf16.h>

// Closed-form reformulation:
//   per_pair = cos^2 * (1 - cos^2) = (1 - cos(4*(theta_i - theta_j))) / 8
//   sum over pairs at node v (unit slots only) = (m^2 - C^2 - S^2) / 16
//   with C = sum cos(4 theta), S = sum sin(4 theta), m = # unit slots.
//   P (denominator) = sum_v n_v*(n_v-1)/2 over ALL slots (incl. zero-vector
//   self-loop slots, which contribute 0 to the numerator).
//   loss = [ sum_v (m^2 - C^2 - S^2) ] / (16 * P)

#define MAXN (1 << 17)   // >= 50000 nodes

__device__ float g_C[MAXN];
__device__ float g_S[MAXN];
__device__ float g_W[MAXN];   // m per node (unit slot count), float
__device__ int   g_N[MAXN];   // n per node (all slots)
__device__ double             g_num;
__device__ unsigned long long g_pairs;

__global__ void zero_kernel(int n) {
    int i = blockIdx.x * blockDim.x + threadIdx.x;
    if (i < n) {
        g_C[i] = 0.f; g_S[i] = 0.f; g_W[i] = 0.f; g_N[i] = 0;
    }
    if (i == 0) { g_num = 0.0; g_pairs = 0ULL; }
}

__global__ void edge_kernel(const float* __restrict__ pos,
                            const int* __restrict__ src,
                            const int* __restrict__ dst,
                            int E) {
    int e = blockIdx.x * blockDim.x + threadIdx.x;
    if (e >= E) return;
    int a = src[e];
    int b = dst[e];
    float2 pa = __ldg(((const float2*)pos) + a);
    float2 pb = __ldg(((const float2*)pos) + b);
    float dx = pb.x - pa.x;
    float dy = pb.y - pa.y;
    float n2 = dx * dx + dy * dy;

    atomicAdd(&g_N[a], 1);
    atomicAdd(&g_N[b], 1);

    if (n2 > 0.f) {
        float inv = rsqrtf(n2);
        float c = dx * inv, s = dy * inv;
        // double-angle twice: (c,s) -> (cos4t, sin4t)
        float c2 = c * c - s * s;
        float s2 = 2.f * c * s;
        float c4 = c2 * c2 - s2 * s2;
        float s4 = 2.f * c2 * s2;
        atomicAdd(&g_C[a], c4);
        atomicAdd(&g_S[a], s4);
        atomicAdd(&g_W[a], 1.f);
        atomicAdd(&g_C[b], c4);
        atomicAdd(&g_S[b], s4);
        atomicAdd(&g_W[b], 1.f);
    }
}

__global__ void node_reduce_kernel(int n) {
    int i = blockIdx.x * blockDim.x + threadIdx.x;
    double num = 0.0;
    unsigned long long p = 0ULL;
    if (i < n) {
        float m = g_W[i];
        float C = g_C[i];
        float S = g_S[i];
        num = (double)m * (double)m - (double)C * (double)C
                                    - (double)S * (double)S;
        long long cnt = (long long)g_N[i];
        p = (unsigned long long)(cnt * (cnt - 1) / 2);
    }

    // warp reduce
    #pragma unroll
    for (int off = 16; off > 0; off >>= 1) {
        num += __shfl_down_sync(0xffffffffu, num, off);
        p   += __shfl_down_sync(0xffffffffu, p, off);
    }

    __shared__ double sh_num[32];
    __shared__ unsigned long long sh_p[32];
    int lane = threadIdx.x & 31;
    int wid  = threadIdx.x >> 5;
    if (lane == 0) { sh_num[wid] = num; sh_p[wid] = p; }
    __syncthreads();

    int nwarps = (blockDim.x + 31) >> 5;
    if (wid == 0) {
        num = (lane < nwarps) ? sh_num[lane] : 0.0;
        p   = (lane < nwarps) ? sh_p[lane]   : 0ULL;
        #pragma unroll
        for (int off = 16; off > 0; off >>= 1) {
            num += __shfl_down_sync(0xffffffffu, num, off);
            p   += __shfl_down_sync(0xffffffffu, p, off);
        }
        if (lane == 0) {
            atomicAdd(&g_num, num);
            atomicAdd(&g_pairs, p);
        }
    }
}

__global__ void finalize_kernel(float* out) {
    double denom = 16.0 * (double)g_pairs;
    out[0] = (denom > 0.0) ? (float)(g_num / denom) : 0.0f;
}

extern "C" void kernel_launch(void* const* d_in, const int* in_sizes, int n_in,
                              void* d_out, int out_size) {
    const float* pos = (const float*)d_in[0];           // (1, N, 2)
    const int* edge_index = (const int*)d_in[2];        // (2, E)
    int N = in_sizes[0] / 2;
    int E = in_sizes[2] / 2;
    const int* src = edge_index;
    const int* dst = edge_index + E;
    float* out = (float*)d_out;

    int tb = 256;
    zero_kernel<<<(N + tb - 1) / tb, tb>>>(N);
    edge_kernel<<<(E + tb - 1) / tb, tb>>>(pos, src, dst, E);
    node_reduce_kernel<<<(N + tb - 1) / tb, tb>>>(N);
    finalize_kernel<<<1, 1>>>(out);
}

// round 2
// speedup vs baseline: 1.6267x; 1.6267x over previous
#include <cuda_runtime.h>
#include <cuda_bf16.h>

// Closed-form: per_pair = cos^2(1-cos^2) = (1 - cos(4*dTheta))/8.
// Per node v with m unit slots, C = sum cos4t, S = sum sin4t:
//   sum over unit-slot pairs = (m^2 - C^2 - S^2)/16
// Denominator P = sum_v n(n-1)/2 over ALL slots (zero-vector self-loop slots
// contribute 0 to the numerator but count toward n).
// State is self-cleaning: zero at module load; reduce kernel re-zeroes after
// reading, so every graph replay starts from zero. No zero pass, no finalize
// pass (last-block pattern).

#define MAXN 65536

__device__ float4 g_CSW[MAXN];   // {C, S, W(unit count), Z(zero count)} per node
__device__ double g_num;
__device__ double g_pairs;
__device__ unsigned int g_done;

__device__ __forceinline__ void red_v4(float4* addr, float a, float b, float c, float d) {
    asm volatile("red.global.add.v4.f32 [%0], {%1, %2, %3, %4};"
                 :: "l"(addr), "f"(a), "f"(b), "f"(c), "f"(d)
                 : "memory");
}

__global__ void edge_kernel(const float2* __restrict__ pos,
                            const int* __restrict__ src,
                            const int* __restrict__ dst,
                            int E) {
    int e = blockIdx.x * blockDim.x + threadIdx.x;
    if (e >= E) return;
    int a = src[e];
    int b = dst[e];
    float2 pa = __ldg(pos + a);
    float2 pb = __ldg(pos + b);
    float dx = pb.x - pa.x;
    float dy = pb.y - pa.y;
    float n2 = dx * dx + dy * dy;

    float c4, s4, w, z;
    if (n2 > 0.f) {
        float inv = rsqrtf(n2);
        float c = dx * inv, s = dy * inv;
        float c2 = c * c - s * s;
        float s2 = 2.f * c * s;
        c4 = c2 * c2 - s2 * s2;
        s4 = 2.f * c2 * s2;
        w = 1.f; z = 0.f;
    } else {
        c4 = 0.f; s4 = 0.f; w = 0.f; z = 1.f;
    }
    red_v4(&g_CSW[a], c4, s4, w, z);
    red_v4(&g_CSW[b], c4, s4, w, z);
}

__global__ void reduce_finalize_kernel(float* __restrict__ out, int n) {
    int i = blockIdx.x * blockDim.x + threadIdx.x;
    double num = 0.0;
    double p = 0.0;
    if (i < n) {
        float4 v = g_CSW[i];
        g_CSW[i] = make_float4(0.f, 0.f, 0.f, 0.f);   // self-clean for next replay
        num = (double)v.z * (double)v.z
            - (double)v.x * (double)v.x
            - (double)v.y * (double)v.y;
        double nn = (double)(v.z + v.w);              // total slot count
        p = 0.5 * nn * (nn - 1.0);
    }

    // warp reduce
    #pragma unroll
    for (int off = 16; off > 0; off >>= 1) {
        num += __shfl_down_sync(0xffffffffu, num, off);
        p   += __shfl_down_sync(0xffffffffu, p, off);
    }

    __shared__ double sh_num[32];
    __shared__ double sh_p[32];
    int lane = threadIdx.x & 31;
    int wid  = threadIdx.x >> 5;
    if (lane == 0) { sh_num[wid] = num; sh_p[wid] = p; }
    __syncthreads();

    int nwarps = (blockDim.x + 31) >> 5;
    if (wid == 0) {
        num = (lane < nwarps) ? sh_num[lane] : 0.0;
        p   = (lane < nwarps) ? sh_p[lane]   : 0.0;
        #pragma unroll
        for (int off = 16; off > 0; off >>= 1) {
            num += __shfl_down_sync(0xffffffffu, num, off);
            p   += __shfl_down_sync(0xffffffffu, p, off);
        }
        if (lane == 0) {
            atomicAdd(&g_num, num);
            atomicAdd(&g_pairs, p);
            __threadfence();
            unsigned int t = atomicAdd(&g_done, 1u);
            if (t == gridDim.x - 1) {
                // last block: all partial sums visible (fence + atomic order)
                double total_num   = atomicAdd(&g_num, 0.0);
                double total_pairs = atomicAdd(&g_pairs, 0.0);
                double denom = 16.0 * total_pairs;
                out[0] = (denom > 0.0) ? (float)(total_num / denom) : 0.0f;
                // reset scalars for next replay
                g_num = 0.0;
                g_pairs = 0.0;
                g_done = 0u;
                __threadfence();
            }
        }
    }
}

extern "C" void kernel_launch(void* const* d_in, const int* in_sizes, int n_in,
                              void* d_out, int out_size) {
    const float* pos = (const float*)d_in[0];       // (1, N, 2)
    const int* edge_index = (const int*)d_in[2];    // (2, E)
    int N = in_sizes[0] / 2;
    int E = in_sizes[2] / 2;
    const int* src = edge_index;
    const int* dst = edge_index + E;
    float* out = (float*)d_out;

    int tb = 256;
    edge_kernel<<<(E + tb - 1) / tb, tb>>>((const float2*)pos, src, dst, E);
    reduce_finalize_kernel<<<(N + tb - 1) / tb, tb>>>(out, N);
}